// round 15
// baseline (speedup 1.0000x reference)
#include <cuda_runtime.h>
#include <cuda_fp16.h>
#include <cstdint>

// Problem constants
#define BATCH 4
#define S_LEN 2048
#define D_MODEL 1024
#define N_HEADS 16
#define HEAD_DIM 64
#define M_ROWS 8192
#define KDIM 1024
#define ALIBI_WIN 56
#define SOFTMAX_REF 8.0f

// ---------------------------------------------------------------------------
// Scratch
// ---------------------------------------------------------------------------
__device__ __align__(16) __half g_qkv16[(size_t)M_ROWS * 3 * D_MODEL];
__device__ __align__(16) __half g_x16[(size_t)M_ROWS * KDIM];
__device__ __align__(16) __half g_a16[(size_t)M_ROWS * KDIM];
__device__ __align__(16) __half g_wq16[(size_t)3 * D_MODEL * KDIM];
__device__ __align__(16) __half g_wo16[(size_t)D_MODEL * KDIM];

// ---------------------------------------------------------------------------
// helpers
// ---------------------------------------------------------------------------
__device__ __forceinline__ uint32_t smem_u32(const void* p) {
    uint32_t a;
    asm("{ .reg .u64 t; cvta.to.shared.u64 t, %1; cvt.u32.u64 %0, t; }"
        : "=r"(a) : "l"(p));
    return a;
}

__device__ __forceinline__ void ldsm_x4(uint32_t (&r)[4], uint32_t addr) {
    asm volatile("ldmatrix.sync.aligned.m8n8.x4.shared.b16 {%0,%1,%2,%3}, [%4];"
                 : "=r"(r[0]), "=r"(r[1]), "=r"(r[2]), "=r"(r[3]) : "r"(addr));
}

__device__ __forceinline__ void ldsm_x4_t(uint32_t (&r)[4], uint32_t addr) {
    asm volatile("ldmatrix.sync.aligned.m8n8.x4.trans.shared.b16 {%0,%1,%2,%3}, [%4];"
                 : "=r"(r[0]), "=r"(r[1]), "=r"(r[2]), "=r"(r[3]) : "r"(addr));
}

__device__ __forceinline__ void mma16816h(float (&c)[4], const uint32_t (&a)[4],
                                          uint32_t b0, uint32_t b1) {
    asm volatile(
        "mma.sync.aligned.m16n8k16.row.col.f32.f16.f16.f32 "
        "{%0,%1,%2,%3}, {%4,%5,%6,%7}, {%8,%9}, {%0,%1,%2,%3};"
        : "+f"(c[0]), "+f"(c[1]), "+f"(c[2]), "+f"(c[3])
        : "r"(a[0]), "r"(a[1]), "r"(a[2]), "r"(a[3]), "r"(b0), "r"(b1));
}

__device__ __forceinline__ float exp_fast(float s) {
    float x = fmaxf(s * 1.44269504089f, -120.f);
    int ii = __float2int_rn(x);
    float f = x - (float)ii;
    float y = f * 0.69314718056f;
    float p = 8.3333333e-3f;
    p = fmaf(p, y, 4.16666667e-2f);
    p = fmaf(p, y, 0.166666667f);
    p = fmaf(p, y, 0.5f);
    p = fmaf(p, y, 1.0f);
    p = fmaf(p, y, 1.0f);
    return __int_as_float(__float_as_int(p) + (ii << 23));
}

__device__ __forceinline__ uint32_t packh2(float a, float b) {
    __half2 h = __floats2half2_rn(a, b);
    return *(uint32_t*)&h;
}

// raw score c (unscaled), distance dist -> exp(c/8 - dist - REF) masked
__device__ __forceinline__ float exp_bias(float c, int dist) {
    bool valid = (unsigned)dist <= (unsigned)ALIBI_WIN;
    float s = valid ? fmaf(c, 0.125f, -(float)dist - SOFTMAX_REF) : -1e30f;
    return exp_fast(s);
}

// ---------------------------------------------------------------------------
// Batched fp32 -> fp16 conversion
// ---------------------------------------------------------------------------
#define N4_X   (M_ROWS * KDIM / 4)
#define N4_WQ  (3 * D_MODEL * KDIM / 4)
#define N4_WO  (D_MODEL * KDIM / 4)
#define N4_ALL (N4_X + N4_WQ + N4_WO)

__global__ __launch_bounds__(256) void convert_f16_all(
    const float* __restrict__ x, const float* __restrict__ wq,
    const float* __restrict__ wo,
    __half* __restrict__ x16, __half* __restrict__ wq16,
    __half* __restrict__ wo16)
{
    int i = blockIdx.x * blockDim.x + threadIdx.x;
    if (i >= N4_ALL) return;
    const float* in;
    __half* o;
    if (i < N4_X)              { in = x;  o = x16;  }
    else if (i < N4_X + N4_WQ) { in = wq; o = wq16; i -= N4_X; }
    else                       { in = wo; o = wo16; i -= N4_X + N4_WQ; }

    float4 f = ((const float4*)in)[i];
    uint2 pk;
    pk.x = packh2(f.x, f.y);
    pk.y = packh2(f.z, f.w);
    ((uint2*)o)[i] = pk;
}

// ---------------------------------------------------------------------------
// fp16 GEMM: 128(M) x 64(N) tile, BK=64, 2-stage, 256 threads, 3 CTAs/SM.
// 8 warps as 4(m) x 2(n), warp tile 32x32 -> 32 acc regs. ROWB=144.
// Dual output: fp16 (C16) or fp32 (C32).
// ---------------------------------------------------------------------------
#define BK 64
#define NCH (KDIM / BK)            // 16
#define ROWB 144
#define A_TILE_B (128 * ROWB)      // 18432
#define B_TILE_B (64 * ROWB)       // 9216
#define STAGE_B (A_TILE_B + B_TILE_B)  // 27648
#define NSTAGE 2
#define SM_TOTAL (NSTAGE * STAGE_B)    // 55296

__global__ __launch_bounds__(256, 3) void tc_gemm_f16(
    const __half* __restrict__ A, const __half* __restrict__ B,
    const float* __restrict__ bias, float* __restrict__ C32,
    __half* __restrict__ C16, int N)
{
    extern __shared__ char sm[];
    const uint32_t sbase = smem_u32(sm);
    const int tid = threadIdx.x;
    const int wid = tid >> 5;
    const int lane = tid & 31;
    const int wr = wid >> 1;          // 0..3 : 32-row block
    const int wc = wid & 1;           // 0..1 : 32-col block
    const int m0 = blockIdx.y * 128;
    const int n0 = blockIdx.x * 64;

    float acc[2][4][4];
#pragma unroll
    for (int i = 0; i < 2; i++)
#pragma unroll
        for (int j = 0; j < 4; j++)
#pragma unroll
            for (int f = 0; f < 4; f++) acc[i][j][f] = 0.f;

    // per stage: A 128x8 + B 64x8 chunks(16B) = 1536 cp.async; 6/thread
    auto load_stage = [&](int kc, int stage) {
        const int kbase = kc * BK;
        const uint32_t sdst = sbase + stage * STAGE_B;
#pragma unroll
        for (int u = 0; u < 6; u++) {
            int idx = u * 256 + tid;
            if (idx < 1024) {
                int r = idx >> 3, ch = idx & 7;
                const void* src = A + (size_t)(m0 + r) * KDIM + kbase + ch * 8;
                uint32_t dst = sdst + r * ROWB + ch * 16;
                asm volatile("cp.async.cg.shared.global [%0], [%1], 16;"
                             :: "r"(dst), "l"(src));
            } else {
                int w = idx - 1024;
                int r = w >> 3, ch = w & 7;
                const void* src = B + (size_t)(n0 + r) * KDIM + kbase + ch * 8;
                uint32_t dst = sdst + A_TILE_B + r * ROWB + ch * 16;
                asm volatile("cp.async.cg.shared.global [%0], [%1], 16;"
                             :: "r"(dst), "l"(src));
            }
        }
        asm volatile("cp.async.commit_group;" ::: "memory");
    };

    load_stage(0, 0);
    load_stage(1, 1);

    const int sub = lane >> 3;
    const int rin = lane & 7;

    for (int c = 0; c < NCH; c++) {
        if (c + 1 < NCH)
            asm volatile("cp.async.wait_group 1;" ::: "memory");
        else
            asm volatile("cp.async.wait_group 0;" ::: "memory");
        __syncthreads();

        const uint32_t sb = sbase + (c & 1) * STAGE_B;
        const uint32_t sA = sb;
        const uint32_t sB = sb + A_TILE_B;

#pragma unroll
        for (int ks = 0; ks < 4; ks++) {
            const int k0 = ks * 16;
            const int am = ((sub & 1) ? 8 : 0) + rin;
            const int ak = k0 + ((sub & 2) ? 8 : 0);
            uint32_t a[2][4];
#pragma unroll
            for (int mt = 0; mt < 2; mt++)
                ldsm_x4(a[mt], sA + (uint32_t)((wr * 32 + mt * 16 + am) * ROWB + ak * 2));
            const int bn = ((sub & 2) ? 8 : 0) + rin;
            const int bk = k0 + ((sub & 1) ? 8 : 0);
            uint32_t bb[2][4];
#pragma unroll
            for (int g = 0; g < 2; g++)
                ldsm_x4(bb[g], sB + (uint32_t)((wc * 32 + g * 16 + bn) * ROWB + bk * 2));
#pragma unroll
            for (int mt = 0; mt < 2; mt++)
#pragma unroll
                for (int nt = 0; nt < 4; nt++) {
                    const int g = nt >> 1, p = (nt & 1) * 2;
                    mma16816h(acc[mt][nt], a[mt], bb[g][p], bb[g][p + 1]);
                }
        }
        __syncthreads();
        if (c + 2 < NCH) load_stage(c + 2, c & 1);
    }

    const int em = lane >> 2;
    const int en = (lane & 3) * 2;
#pragma unroll
    for (int mt = 0; mt < 2; mt++) {
#pragma unroll
        for (int nt = 0; nt < 4; nt++) {
            int n = n0 + wc * 32 + nt * 8 + en;
            float b0 = bias[n], b1 = bias[n + 1];
            int m = m0 + wr * 32 + mt * 16 + em;
            float o00 = acc[mt][nt][0] + b0, o01 = acc[mt][nt][1] + b1;
            float o10 = acc[mt][nt][2] + b0, o11 = acc[mt][nt][3] + b1;
            if (C16) {
                *(uint32_t*)(C16 + (size_t)m * N + n) = packh2(o00, o01);
                *(uint32_t*)(C16 + (size_t)(m + 8) * N + n) = packh2(o10, o11);
            } else {
                *(float2*)(C32 + (size_t)m * N + n) = make_float2(o00, o01);
                *(float2*)(C32 + (size_t)(m + 8) * N + n) = make_float2(o10, o11);
            }
        }
    }
}

// ---------------------------------------------------------------------------
// Tensor-core windowed attention (round-13 proven, all fp16, cp.async)
// ---------------------------------------------------------------------------
#define AROWB 144
#define VROWB 176
#define OFF_Q  0
#define OFF_K  9216
#define OFF_V  27648
#define SM_ATT (OFF_V + 128 * VROWB)

__global__ __launch_bounds__(128) void attn_mma(
    const __half* __restrict__ qkv, __half* __restrict__ aout)
{
    extern __shared__ char sm[];
    const uint32_t sbase = smem_u32(sm);
    const int b = blockIdx.z;
    const int h = blockIdx.y;
    const int qt = blockIdx.x;
    const int q0 = qt * 64;
    const int tid = threadIdx.x;
    const int wid = tid >> 5;
    const int lane = tid & 31;

    const __half* qkvb = qkv + (size_t)(b * S_LEN) * (3 * D_MODEL) + h * HEAD_DIM;
    const int kskip = (qt == 0) ? 64 : 0;

#pragma unroll
    for (int u = 0; u < 4; u++) {                      // Q
        int idx = u * 128 + tid;
        int r = idx >> 3, ch = idx & 7;
        const void* src = qkvb + (size_t)(q0 + r) * (3 * D_MODEL) + ch * 8;
        uint32_t dst = sbase + OFF_Q + r * AROWB + ch * 16;
        asm volatile("cp.async.cg.shared.global [%0], [%1], 16;" :: "r"(dst), "l"(src));
    }
#pragma unroll
    for (int u = 0; u < 8; u++) {                      // K
        int idx = u * 128 + tid;
        int r = idx >> 3, ch = idx & 7;
        if (r >= kskip) {
            const void* src = qkvb + (size_t)(q0 - 64 + r) * (3 * D_MODEL)
                              + D_MODEL + ch * 8;
            uint32_t dst = sbase + OFF_K + r * AROWB + ch * 16;
            asm volatile("cp.async.cg.shared.global [%0], [%1], 16;" :: "r"(dst), "l"(src));
        }
    }
#pragma unroll
    for (int u = 0; u < 8; u++) {                      // V
        int idx = u * 128 + tid;
        int r = idx >> 3, ch = idx & 7;
        if (r >= kskip) {
            const void* src = qkvb + (size_t)(q0 - 64 + r) * (3 * D_MODEL)
                              + 2 * D_MODEL + ch * 8;
            uint32_t dst = sbase + OFF_V + r * VROWB + ch * 16;
            asm volatile("cp.async.cg.shared.global [%0], [%1], 16;" :: "r"(dst), "l"(src));
        }
    }
    {
        uint32_t onezero = packh2(1.0f, 0.0f);
#pragma unroll
        for (int u = 0; u < 8; u++) {
            int w = u * 128 + tid;
            int r = w >> 3, cw = w & 7;
            *(uint32_t*)(sm + OFF_V + r * VROWB + 128 + cw * 4) = cw ? 0u : onezero;
        }
    }
    asm volatile("cp.async.commit_group;" ::: "memory");
    asm volatile("cp.async.wait_group 0;" ::: "memory");
    __syncthreads();

    const int sub = lane >> 3;
    const int rin = lane & 7;

    uint32_t qa[4][4];
    {
        const int am = wid * 16 + ((sub & 1) ? 8 : 0) + rin;
#pragma unroll
        for (int ks = 0; ks < 4; ks++) {
            int ak = ks * 16 + ((sub & 2) ? 8 : 0);
            ldsm_x4(qa[ks], sbase + OFF_Q + am * AROWB + ak * 2);
        }
    }

    float out[9][4];
#pragma unroll
    for (int n = 0; n < 9; n++)
#pragma unroll
        for (int f = 0; f < 4; f++) out[n][f] = 0.f;

    const int ktstart = (qt == 0) ? 1 : 0;
    const int qr = q0 + wid * 16 + (lane >> 2);

    for (int kt = ktstart; kt < 2; kt++) {
#pragma unroll
        for (int nt2 = 0; nt2 < 4; nt2++) {
            const int krowbase = kt * 64 + nt2 * 16;

            uint32_t kb[4][4];
            {
                const int bn = krowbase + ((sub & 2) ? 8 : 0) + rin;
                const int bkoff = ((sub & 1) ? 8 : 0);
#pragma unroll
                for (int ks = 0; ks < 4; ks++)
                    ldsm_x4(kb[ks], sbase + OFF_K
                            + (uint32_t)(bn * AROWB + (ks * 16 + bkoff) * 2));
            }

            float s[2][4];
#pragma unroll
            for (int ntl = 0; ntl < 2; ntl++)
#pragma unroll
                for (int f = 0; f < 4; f++) s[ntl][f] = 0.f;
#pragma unroll
            for (int ks = 0; ks < 4; ks++)
#pragma unroll
                for (int ntl = 0; ntl < 2; ntl++)
                    mma16816h(s[ntl], qa[ks], kb[ks][ntl * 2], kb[ks][ntl * 2 + 1]);

            uint32_t pa[4];
#pragma unroll
            for (int ntl = 0; ntl < 2; ntl++) {
                const int key = q0 - 64 + krowbase + ntl * 8 + (lane & 3) * 2;
                float p0 = exp_bias(s[ntl][0], qr - key);
                float p1 = exp_bias(s[ntl][1], qr - key - 1);
                float p2 = exp_bias(s[ntl][2], qr + 8 - key);
                float p3 = exp_bias(s[ntl][3], qr + 8 - key - 1);
                pa[ntl * 2 + 0] = packh2(p0, p1);
                pa[ntl * 2 + 1] = packh2(p2, p3);
            }

            {
                const int vrow = krowbase + ((sub & 1) ? 8 : 0) + rin;
#pragma unroll
                for (int g = 0; g < 5; g++) {
                    uint32_t vb[4];
                    int vcol = g * 16 + ((sub & 2) ? 8 : 0);
                    ldsm_x4_t(vb, sbase + OFF_V + (uint32_t)(vrow * VROWB + vcol * 2));
                    if (g < 4) {
                        mma16816h(out[g * 2 + 0], pa, vb[0], vb[1]);
                        mma16816h(out[g * 2 + 1], pa, vb[2], vb[3]);
                    } else {
                        mma16816h(out[8], pa, vb[0], vb[1]);
                    }
                }
            }
        }
    }

    float lv01 = __shfl_sync(0xffffffffu, out[8][0], lane & ~3);
    float lv23 = __shfl_sync(0xffffffffu, out[8][2], lane & ~3);
    const float inv01 = 1.f / lv01;
    const float inv23 = 1.f / lv23;

    const size_t r0base = ((size_t)(b * S_LEN) + qr) * KDIM + h * HEAD_DIM;
    const size_t r1base = r0base + (size_t)8 * KDIM;
#pragma unroll
    for (int n = 0; n < 8; n++) {
        const int dcol = n * 8 + (lane & 3) * 2;
        *(uint32_t*)(aout + r0base + dcol) = packh2(out[n][0] * inv01, out[n][1] * inv01);
        *(uint32_t*)(aout + r1base + dcol) = packh2(out[n][2] * inv23, out[n][3] * inv23);
    }
}

// ---------------------------------------------------------------------------
// Launch
// ---------------------------------------------------------------------------
extern "C" void kernel_launch(void* const* d_in, const int* in_sizes, int n_in,
                              void* d_out, int out_size)
{
    const float* x     = (const float*)d_in[0];
    const float* w_qkv = (const float*)d_in[1];
    const float* b_qkv = (const float*)d_in[2];
    const float* w_out = (const float*)d_in[3];
    const float* b_out = (const float*)d_in[4];
    float* out = (float*)d_out;

    __half *qkv16, *x16, *a16, *wq16, *wo16;
    cudaGetSymbolAddress((void**)&qkv16, g_qkv16);
    cudaGetSymbolAddress((void**)&x16, g_x16);
    cudaGetSymbolAddress((void**)&a16, g_a16);
    cudaGetSymbolAddress((void**)&wq16, g_wq16);
    cudaGetSymbolAddress((void**)&wo16, g_wo16);

    cudaFuncSetAttribute(tc_gemm_f16, cudaFuncAttributeMaxDynamicSharedMemorySize, SM_TOTAL);
    cudaFuncSetAttribute(attn_mma, cudaFuncAttributeMaxDynamicSharedMemorySize, SM_ATT);

    // 0) fp32 -> fp16
    convert_f16_all<<<(N4_ALL + 255) / 256, 256>>>(x, w_qkv, w_out, x16, wq16, wo16);

    // 1) QKV projection -> fp16 qkv buffer
    {
        dim3 grid(3 * D_MODEL / 64, M_ROWS / 128);    // (48, 64)
        tc_gemm_f16<<<grid, 256, SM_TOTAL>>>(x16, wq16, b_qkv, nullptr, qkv16,
                                             3 * D_MODEL);
    }

    // 2) Tensor-core windowed attention (fp16 in, fp16 out)
    {
        dim3 grid(S_LEN / 64, N_HEADS, BATCH);
        attn_mma<<<grid, 128, SM_ATT>>>(qkv16, a16);
    }

    // 3) Output projection -> fp32 d_out
    {
        dim3 grid(D_MODEL / 64, M_ROWS / 128);        // (16, 64)
        tc_gemm_f16<<<grid, 256, SM_TOTAL>>>(a16, wo16, b_out, out, nullptr, D_MODEL);
    }
}

// round 16
// speedup vs baseline: 1.0527x; 1.0527x over previous
#include <cuda_runtime.h>
#include <cuda_fp16.h>
#include <cstdint>

// Problem constants
#define BATCH 4
#define S_LEN 2048
#define D_MODEL 1024
#define N_HEADS 16
#define HEAD_DIM 64
#define M_ROWS 8192
#define KDIM 1024
#define ALIBI_WIN 56
#define SOFTMAX_REF 8.0f

// ---------------------------------------------------------------------------
// Scratch
// ---------------------------------------------------------------------------
__device__ __align__(16) __half g_qkv16[(size_t)M_ROWS * 3 * D_MODEL];
__device__ __align__(16) __half g_x16[(size_t)M_ROWS * KDIM];
__device__ __align__(16) __half g_a16[(size_t)M_ROWS * KDIM];
__device__ __align__(16) __half g_wq16[(size_t)3 * D_MODEL * KDIM];
__device__ __align__(16) __half g_wo16[(size_t)D_MODEL * KDIM];

// ---------------------------------------------------------------------------
// helpers
// ---------------------------------------------------------------------------
__device__ __forceinline__ uint32_t smem_u32(const void* p) {
    uint32_t a;
    asm("{ .reg .u64 t; cvta.to.shared.u64 t, %1; cvt.u32.u64 %0, t; }"
        : "=r"(a) : "l"(p));
    return a;
}

__device__ __forceinline__ void ldsm_x4(uint32_t (&r)[4], uint32_t addr) {
    asm volatile("ldmatrix.sync.aligned.m8n8.x4.shared.b16 {%0,%1,%2,%3}, [%4];"
                 : "=r"(r[0]), "=r"(r[1]), "=r"(r[2]), "=r"(r[3]) : "r"(addr));
}

__device__ __forceinline__ void ldsm_x4_t(uint32_t (&r)[4], uint32_t addr) {
    asm volatile("ldmatrix.sync.aligned.m8n8.x4.trans.shared.b16 {%0,%1,%2,%3}, [%4];"
                 : "=r"(r[0]), "=r"(r[1]), "=r"(r[2]), "=r"(r[3]) : "r"(addr));
}

__device__ __forceinline__ void mma16816h(float (&c)[4], const uint32_t (&a)[4],
                                          uint32_t b0, uint32_t b1) {
    asm volatile(
        "mma.sync.aligned.m16n8k16.row.col.f32.f16.f16.f32 "
        "{%0,%1,%2,%3}, {%4,%5,%6,%7}, {%8,%9}, {%0,%1,%2,%3};"
        : "+f"(c[0]), "+f"(c[1]), "+f"(c[2]), "+f"(c[3])
        : "r"(a[0]), "r"(a[1]), "r"(a[2]), "r"(a[3]), "r"(b0), "r"(b1));
}

__device__ __forceinline__ float exp_fast(float s) {
    float x = fmaxf(s * 1.44269504089f, -120.f);
    int ii = __float2int_rn(x);
    float f = x - (float)ii;
    float y = f * 0.69314718056f;
    float p = 8.3333333e-3f;
    p = fmaf(p, y, 4.16666667e-2f);
    p = fmaf(p, y, 0.166666667f);
    p = fmaf(p, y, 0.5f);
    p = fmaf(p, y, 1.0f);
    p = fmaf(p, y, 1.0f);
    return __int_as_float(__float_as_int(p) + (ii << 23));
}

__device__ __forceinline__ uint32_t packh2(float a, float b) {
    __half2 h = __floats2half2_rn(a, b);
    return *(uint32_t*)&h;
}

// raw score c (unscaled), distance dist -> exp(c/8 - dist - REF) masked
__device__ __forceinline__ float exp_bias(float c, int dist) {
    bool valid = (unsigned)dist <= (unsigned)ALIBI_WIN;
    float s = valid ? fmaf(c, 0.125f, -(float)dist - SOFTMAX_REF) : -1e30f;
    return exp_fast(s);
}

// ---------------------------------------------------------------------------
// Batched fp32 -> fp16 conversion, 2 float4 per thread (ILP 2)
// ---------------------------------------------------------------------------
#define N4_X   (M_ROWS * KDIM / 4)
#define N4_WQ  (3 * D_MODEL * KDIM / 4)
#define N4_WO  (D_MODEL * KDIM / 4)
#define N4_ALL (N4_X + N4_WQ + N4_WO)
#define CVT_PER (N4_ALL / 2)

__global__ __launch_bounds__(256) void convert_f16_all(
    const float* __restrict__ x, const float* __restrict__ wq,
    const float* __restrict__ wo,
    __half* __restrict__ x16, __half* __restrict__ wq16,
    __half* __restrict__ wo16)
{
    int base = blockIdx.x * blockDim.x + threadIdx.x;
#pragma unroll
    for (int rep = 0; rep < 2; rep++) {
        int i = base + rep * CVT_PER;
        if (i >= N4_ALL) return;
        const float* in;
        __half* o;
        int j = i;
        if (j < N4_X)              { in = x;  o = x16;  }
        else if (j < N4_X + N4_WQ) { in = wq; o = wq16; j -= N4_X; }
        else                       { in = wo; o = wo16; j -= N4_X + N4_WQ; }

        float4 f = ((const float4*)in)[j];
        uint2 pk;
        pk.x = packh2(f.x, f.y);
        pk.y = packh2(f.z, f.w);
        ((uint2*)o)[j] = pk;
    }
}

// ---------------------------------------------------------------------------
// fp16 GEMM, BK=64, 3-stage cp.async pipeline, 2 CTAs/SM (round-14 proven).
// ROWB=144 (9 x 16B) -> conflict-free ldmatrix. 16 chunks, 64 HMMA/warp/chunk.
// Dual output: fp16 (C16) or fp32 (C32).
// ---------------------------------------------------------------------------
#define BK 64
#define NCH (KDIM / BK)            // 16
#define ROWB 144
#define TILE_B (128 * ROWB)        // 18432
#define STAGE_B (2 * TILE_B)       // 36864
#define NSTAGE 3
#define SM_TOTAL (NSTAGE * STAGE_B)  // 110592

__global__ __launch_bounds__(256, 2) void tc_gemm_f16(
    const __half* __restrict__ A, const __half* __restrict__ B,
    const float* __restrict__ bias, float* __restrict__ C32,
    __half* __restrict__ C16, int N)
{
    extern __shared__ char sm[];
    const uint32_t sbase = smem_u32(sm);
    const int tid = threadIdx.x;
    const int wid = tid >> 5;
    const int lane = tid & 31;
    const int wr = wid >> 2;
    const int wc = wid & 3;
    const int m0 = blockIdx.y * 128;
    const int n0 = blockIdx.x * 128;

    float acc[4][4][4];
#pragma unroll
    for (int i = 0; i < 4; i++)
#pragma unroll
        for (int j = 0; j < 4; j++)
#pragma unroll
            for (int f = 0; f < 4; f++) acc[i][j][f] = 0.f;

    // per stage: 2 tiles x 128 rows x 8 chunks(16B) = 2048 cp.async; 8/thread
    auto load_stage = [&](int kc, int stage) {
        const int kbase = kc * BK;
        const uint32_t sdst = sbase + stage * STAGE_B;
#pragma unroll
        for (int u = 0; u < 8; u++) {
            int idx = u * 256 + tid;
            int t = idx >> 10;
            int within = idx & 1023;
            int r = within >> 3;
            int ch = within & 7;
            const __half* base = (t == 0) ? A : B;
            int grow = ((t == 0) ? m0 : n0) + r;
            const void* src = base + (size_t)grow * KDIM + kbase + ch * 8;
            uint32_t dst = sdst + t * TILE_B + r * ROWB + ch * 16;
            asm volatile("cp.async.cg.shared.global [%0], [%1], 16;"
                         :: "r"(dst), "l"(src));
        }
        asm volatile("cp.async.commit_group;" ::: "memory");
    };

    load_stage(0, 0);
    load_stage(1, 1);

    const int sub = lane >> 3;
    const int rin = lane & 7;

    int stage = 0;          // stage of chunk c
    int pstage = 2;         // stage for prefetched chunk c+2
    for (int c = 0; c < NCH; c++) {
        asm volatile("cp.async.wait_group 1;" ::: "memory");
        __syncthreads();

        // prefetch c+2 into the stage last read at chunk c-1 (all warps past it)
        if (c + 2 < NCH)
            load_stage(c + 2, pstage);
        else
            asm volatile("cp.async.commit_group;" ::: "memory");

        const uint32_t sb = sbase + stage * STAGE_B;
        const uint32_t sA = sb;
        const uint32_t sB = sb + TILE_B;

#pragma unroll
        for (int ks = 0; ks < 4; ks++) {
            const int k0 = ks * 16;
            const int am = ((sub & 1) ? 8 : 0) + rin;
            const int ak = k0 + ((sub & 2) ? 8 : 0);
            uint32_t a[4][4];
#pragma unroll
            for (int mt = 0; mt < 4; mt++)
                ldsm_x4(a[mt], sA + (uint32_t)((wr * 64 + mt * 16 + am) * ROWB + ak * 2));
            const int bn = ((sub & 2) ? 8 : 0) + rin;
            const int bk = k0 + ((sub & 1) ? 8 : 0);
            uint32_t bb[2][4];
#pragma unroll
            for (int g = 0; g < 2; g++)
                ldsm_x4(bb[g], sB + (uint32_t)((wc * 32 + g * 16 + bn) * ROWB + bk * 2));
#pragma unroll
            for (int mt = 0; mt < 4; mt++)
#pragma unroll
                for (int nt = 0; nt < 4; nt++) {
                    const int g = nt >> 1, p = (nt & 1) * 2;
                    mma16816h(acc[mt][nt], a[mt], bb[g][p], bb[g][p + 1]);
                }
        }
        stage = (stage + 1 == NSTAGE) ? 0 : stage + 1;
        pstage = (pstage + 1 == NSTAGE) ? 0 : pstage + 1;
    }

    const int em = lane >> 2;
    const int en = (lane & 3) * 2;
#pragma unroll
    for (int mt = 0; mt < 4; mt++) {
#pragma unroll
        for (int nt = 0; nt < 4; nt++) {
            int n = n0 + wc * 32 + nt * 8 + en;
            float b0 = bias[n], b1 = bias[n + 1];
            int m = m0 + wr * 64 + mt * 16 + em;
            float o00 = acc[mt][nt][0] + b0, o01 = acc[mt][nt][1] + b1;
            float o10 = acc[mt][nt][2] + b0, o11 = acc[mt][nt][3] + b1;
            if (C16) {
                *(uint32_t*)(C16 + (size_t)m * N + n) = packh2(o00, o01);
                *(uint32_t*)(C16 + (size_t)(m + 8) * N + n) = packh2(o10, o11);
            } else {
                *(float2*)(C32 + (size_t)m * N + n) = make_float2(o00, o01);
                *(float2*)(C32 + (size_t)(m + 8) * N + n) = make_float2(o10, o11);
            }
        }
    }
}

// ---------------------------------------------------------------------------
// Tensor-core windowed attention (round-13 proven, all fp16, cp.async)
// ---------------------------------------------------------------------------
#define AROWB 144
#define VROWB 176
#define OFF_Q  0
#define OFF_K  9216
#define OFF_V  27648
#define SM_ATT (OFF_V + 128 * VROWB)

__global__ __launch_bounds__(128) void attn_mma(
    const __half* __restrict__ qkv, __half* __restrict__ aout)
{
    extern __shared__ char sm[];
    const uint32_t sbase = smem_u32(sm);
    const int b = blockIdx.z;
    const int h = blockIdx.y;
    const int qt = blockIdx.x;
    const int q0 = qt * 64;
    const int tid = threadIdx.x;
    const int wid = tid >> 5;
    const int lane = tid & 31;

    const __half* qkvb = qkv + (size_t)(b * S_LEN) * (3 * D_MODEL) + h * HEAD_DIM;
    const int kskip = (qt == 0) ? 64 : 0;

#pragma unroll
    for (int u = 0; u < 4; u++) {                      // Q
        int idx = u * 128 + tid;
        int r = idx >> 3, ch = idx & 7;
        const void* src = qkvb + (size_t)(q0 + r) * (3 * D_MODEL) + ch * 8;
        uint32_t dst = sbase + OFF_Q + r * AROWB + ch * 16;
        asm volatile("cp.async.cg.shared.global [%0], [%1], 16;" :: "r"(dst), "l"(src));
    }
#pragma unroll
    for (int u = 0; u < 8; u++) {                      // K
        int idx = u * 128 + tid;
        int r = idx >> 3, ch = idx & 7;
        if (r >= kskip) {
            const void* src = qkvb + (size_t)(q0 - 64 + r) * (3 * D_MODEL)
                              + D_MODEL + ch * 8;
            uint32_t dst = sbase + OFF_K + r * AROWB + ch * 16;
            asm volatile("cp.async.cg.shared.global [%0], [%1], 16;" :: "r"(dst), "l"(src));
        }
    }
#pragma unroll
    for (int u = 0; u < 8; u++) {                      // V
        int idx = u * 128 + tid;
        int r = idx >> 3, ch = idx & 7;
        if (r >= kskip) {
            const void* src = qkvb + (size_t)(q0 - 64 + r) * (3 * D_MODEL)
                              + 2 * D_MODEL + ch * 8;
            uint32_t dst = sbase + OFF_V + r * VROWB + ch * 16;
            asm volatile("cp.async.cg.shared.global [%0], [%1], 16;" :: "r"(dst), "l"(src));
        }
    }
    {
        uint32_t onezero = packh2(1.0f, 0.0f);
#pragma unroll
        for (int u = 0; u < 8; u++) {
            int w = u * 128 + tid;
            int r = w >> 3, cw = w & 7;
            *(uint32_t*)(sm + OFF_V + r * VROWB + 128 + cw * 4) = cw ? 0u : onezero;
        }
    }
    asm volatile("cp.async.commit_group;" ::: "memory");
    asm volatile("cp.async.wait_group 0;" ::: "memory");
    __syncthreads();

    const int sub = lane >> 3;
    const int rin = lane & 7;

    uint32_t qa[4][4];
    {
        const int am = wid * 16 + ((sub & 1) ? 8 : 0) + rin;
#pragma unroll
        for (int ks = 0; ks < 4; ks++) {
            int ak = ks * 16 + ((sub & 2) ? 8 : 0);
            ldsm_x4(qa[ks], sbase + OFF_Q + am * AROWB + ak * 2);
        }
    }

    float out[9][4];
#pragma unroll
    for (int n = 0; n < 9; n++)
#pragma unroll
        for (int f = 0; f < 4; f++) out[n][f] = 0.f;

    const int ktstart = (qt == 0) ? 1 : 0;
    const int qr = q0 + wid * 16 + (lane >> 2);

    for (int kt = ktstart; kt < 2; kt++) {
#pragma unroll
        for (int nt2 = 0; nt2 < 4; nt2++) {
            const int krowbase = kt * 64 + nt2 * 16;

            uint32_t kb[4][4];
            {
                const int bn = krowbase + ((sub & 2) ? 8 : 0) + rin;
                const int bkoff = ((sub & 1) ? 8 : 0);
#pragma unroll
                for (int ks = 0; ks < 4; ks++)
                    ldsm_x4(kb[ks], sbase + OFF_K
                            + (uint32_t)(bn * AROWB + (ks * 16 + bkoff) * 2));
            }

            float s[2][4];
#pragma unroll
            for (int ntl = 0; ntl < 2; ntl++)
#pragma unroll
                for (int f = 0; f < 4; f++) s[ntl][f] = 0.f;
#pragma unroll
            for (int ks = 0; ks < 4; ks++)
#pragma unroll
                for (int ntl = 0; ntl < 2; ntl++)
                    mma16816h(s[ntl], qa[ks], kb[ks][ntl * 2], kb[ks][ntl * 2 + 1]);

            uint32_t pa[4];
#pragma unroll
            for (int ntl = 0; ntl < 2; ntl++) {
                const int key = q0 - 64 + krowbase + ntl * 8 + (lane & 3) * 2;
                float p0 = exp_bias(s[ntl][0], qr - key);
                float p1 = exp_bias(s[ntl][1], qr - key - 1);
                float p2 = exp_bias(s[ntl][2], qr + 8 - key);
                float p3 = exp_bias(s[ntl][3], qr + 8 - key - 1);
                pa[ntl * 2 + 0] = packh2(p0, p1);
                pa[ntl * 2 + 1] = packh2(p2, p3);
            }

            {
                const int vrow = krowbase + ((sub & 1) ? 8 : 0) + rin;
#pragma unroll
                for (int g = 0; g < 5; g++) {
                    uint32_t vb[4];
                    int vcol = g * 16 + ((sub & 2) ? 8 : 0);
                    ldsm_x4_t(vb, sbase + OFF_V + (uint32_t)(vrow * VROWB + vcol * 2));
                    if (g < 4) {
                        mma16816h(out[g * 2 + 0], pa, vb[0], vb[1]);
                        mma16816h(out[g * 2 + 1], pa, vb[2], vb[3]);
                    } else {
                        mma16816h(out[8], pa, vb[0], vb[1]);
                    }
                }
            }
        }
    }

    float lv01 = __shfl_sync(0xffffffffu, out[8][0], lane & ~3);
    float lv23 = __shfl_sync(0xffffffffu, out[8][2], lane & ~3);
    const float inv01 = 1.f / lv01;
    const float inv23 = 1.f / lv23;

    const size_t r0base = ((size_t)(b * S_LEN) + qr) * KDIM + h * HEAD_DIM;
    const size_t r1base = r0base + (size_t)8 * KDIM;
#pragma unroll
    for (int n = 0; n < 8; n++) {
        const int dcol = n * 8 + (lane & 3) * 2;
        *(uint32_t*)(aout + r0base + dcol) = packh2(out[n][0] * inv01, out[n][1] * inv01);
        *(uint32_t*)(aout + r1base + dcol) = packh2(out[n][2] * inv23, out[n][3] * inv23);
    }
}

// ---------------------------------------------------------------------------
// Launch
// ---------------------------------------------------------------------------
extern "C" void kernel_launch(void* const* d_in, const int* in_sizes, int n_in,
                              void* d_out, int out_size)
{
    const float* x     = (const float*)d_in[0];
    const float* w_qkv = (const float*)d_in[1];
    const float* b_qkv = (const float*)d_in[2];
    const float* w_out = (const float*)d_in[3];
    const float* b_out = (const float*)d_in[4];
    float* out = (float*)d_out;

    __half *qkv16, *x16, *a16, *wq16, *wo16;
    cudaGetSymbolAddress((void**)&qkv16, g_qkv16);
    cudaGetSymbolAddress((void**)&x16, g_x16);
    cudaGetSymbolAddress((void**)&a16, g_a16);
    cudaGetSymbolAddress((void**)&wq16, g_wq16);
    cudaGetSymbolAddress((void**)&wo16, g_wo16);

    cudaFuncSetAttribute(tc_gemm_f16, cudaFuncAttributeMaxDynamicSharedMemorySize, SM_TOTAL);
    cudaFuncSetAttribute(attn_mma, cudaFuncAttributeMaxDynamicSharedMemorySize, SM_ATT);

    // 0) fp32 -> fp16 (ILP-2 convert)
    convert_f16_all<<<(CVT_PER + 255) / 256, 256>>>(x, w_qkv, w_out, x16, wq16, wo16);

    // 1) QKV projection -> fp16 qkv buffer
    {
        dim3 grid(3 * D_MODEL / 128, M_ROWS / 128);   // (24, 64)
        tc_gemm_f16<<<grid, 256, SM_TOTAL>>>(x16, wq16, b_qkv, nullptr, qkv16,
                                             3 * D_MODEL);
    }

    // 2) Tensor-core windowed attention (fp16 in, fp16 out)
    {
        dim3 grid(S_LEN / 64, N_HEADS, BATCH);
        attn_mma<<<grid, 128, SM_ATT>>>(qkv16, a16);
    }

    // 3) Output projection -> fp32 d_out
    {
        dim3 grid(D_MODEL / 128, M_ROWS / 128);       // (8, 64)
        tc_gemm_f16<<<grid, 256, SM_TOTAL>>>(a16, wo16, b_out, out, nullptr, D_MODEL);
    }
}

// round 17
// speedup vs baseline: 1.0640x; 1.0107x over previous
#include <cuda_runtime.h>
#include <cuda_fp16.h>
#include <cstdint>

// Problem constants
#define BATCH 4
#define S_LEN 2048
#define D_MODEL 1024
#define N_HEADS 16
#define HEAD_DIM 64
#define M_ROWS 8192
#define KDIM 1024
#define ALIBI_WIN 56
#define SOFTMAX_REF 8.0f

// ---------------------------------------------------------------------------
// Scratch
// ---------------------------------------------------------------------------
__device__ __align__(16) __half g_qkv16[(size_t)M_ROWS * 3 * D_MODEL];
__device__ __align__(16) __half g_x16[(size_t)M_ROWS * KDIM];
__device__ __align__(16) __half g_a16[(size_t)M_ROWS * KDIM];
__device__ __align__(16) __half g_wq16[(size_t)3 * D_MODEL * KDIM];
__device__ __align__(16) __half g_wo16[(size_t)D_MODEL * KDIM];

// ---------------------------------------------------------------------------
// helpers
// ---------------------------------------------------------------------------
__device__ __forceinline__ uint32_t smem_u32(const void* p) {
    uint32_t a;
    asm("{ .reg .u64 t; cvta.to.shared.u64 t, %1; cvt.u32.u64 %0, t; }"
        : "=r"(a) : "l"(p));
    return a;
}

__device__ __forceinline__ void ldsm_x4(uint32_t (&r)[4], uint32_t addr) {
    asm volatile("ldmatrix.sync.aligned.m8n8.x4.shared.b16 {%0,%1,%2,%3}, [%4];"
                 : "=r"(r[0]), "=r"(r[1]), "=r"(r[2]), "=r"(r[3]) : "r"(addr));
}

__device__ __forceinline__ void ldsm_x4_t(uint32_t (&r)[4], uint32_t addr) {
    asm volatile("ldmatrix.sync.aligned.m8n8.x4.trans.shared.b16 {%0,%1,%2,%3}, [%4];"
                 : "=r"(r[0]), "=r"(r[1]), "=r"(r[2]), "=r"(r[3]) : "r"(addr));
}

__device__ __forceinline__ void mma16816h(float (&c)[4], const uint32_t (&a)[4],
                                          uint32_t b0, uint32_t b1) {
    asm volatile(
        "mma.sync.aligned.m16n8k16.row.col.f32.f16.f16.f32 "
        "{%0,%1,%2,%3}, {%4,%5,%6,%7}, {%8,%9}, {%0,%1,%2,%3};"
        : "+f"(c[0]), "+f"(c[1]), "+f"(c[2]), "+f"(c[3])
        : "r"(a[0]), "r"(a[1]), "r"(a[2]), "r"(a[3]), "r"(b0), "r"(b1));
}

__device__ __forceinline__ float exp_fast(float s) {
    float x = fmaxf(s * 1.44269504089f, -120.f);
    int ii = __float2int_rn(x);
    float f = x - (float)ii;
    float y = f * 0.69314718056f;
    float p = 8.3333333e-3f;
    p = fmaf(p, y, 4.16666667e-2f);
    p = fmaf(p, y, 0.166666667f);
    p = fmaf(p, y, 0.5f);
    p = fmaf(p, y, 1.0f);
    p = fmaf(p, y, 1.0f);
    return __int_as_float(__float_as_int(p) + (ii << 23));
}

__device__ __forceinline__ uint32_t packh2(float a, float b) {
    __half2 h = __floats2half2_rn(a, b);
    return *(uint32_t*)&h;
}

// raw score c (unscaled), distance dist -> exp(c/8 - dist - REF) masked
__device__ __forceinline__ float exp_bias(float c, int dist) {
    bool valid = (unsigned)dist <= (unsigned)ALIBI_WIN;
    float s = valid ? fmaf(c, 0.125f, -(float)dist - SOFTMAX_REF) : -1e30f;
    return exp_fast(s);
}

// ---------------------------------------------------------------------------
// Batched fp32 -> fp16 conversion, 2 float4 per thread
// ---------------------------------------------------------------------------
#define N4_X   (M_ROWS * KDIM / 4)
#define N4_WQ  (3 * D_MODEL * KDIM / 4)
#define N4_WO  (D_MODEL * KDIM / 4)
#define N4_ALL (N4_X + N4_WQ + N4_WO)
#define CVT_PER (N4_ALL / 2)

__global__ __launch_bounds__(256) void convert_f16_all(
    const float* __restrict__ x, const float* __restrict__ wq,
    const float* __restrict__ wo,
    __half* __restrict__ x16, __half* __restrict__ wq16,
    __half* __restrict__ wo16)
{
    int base = blockIdx.x * blockDim.x + threadIdx.x;
#pragma unroll
    for (int rep = 0; rep < 2; rep++) {
        int i = base + rep * CVT_PER;
        if (i >= N4_ALL) return;
        const float* in;
        __half* o;
        int j = i;
        if (j < N4_X)              { in = x;  o = x16;  }
        else if (j < N4_X + N4_WQ) { in = wq; o = wq16; j -= N4_X; }
        else                       { in = wo; o = wo16; j -= N4_X + N4_WQ; }

        float4 f = ((const float4*)in)[j];
        uint2 pk;
        pk.x = packh2(f.x, f.y);
        pk.y = packh2(f.z, f.w);
        ((uint2*)o)[j] = pk;
    }
}

// ---------------------------------------------------------------------------
// fp16 GEMM, BK=64, 3-stage cp.async pipeline, 2 CTAs/SM (round-14 proven).
// ---------------------------------------------------------------------------
#define BK 64
#define NCH (KDIM / BK)            // 16
#define ROWB 144
#define TILE_B (128 * ROWB)        // 18432
#define STAGE_B (2 * TILE_B)       // 36864
#define NSTAGE 3
#define SM_TOTAL (NSTAGE * STAGE_B)  // 110592

__global__ __launch_bounds__(256, 2) void tc_gemm_f16(
    const __half* __restrict__ A, const __half* __restrict__ B,
    const float* __restrict__ bias, float* __restrict__ C32,
    __half* __restrict__ C16, int N)
{
    extern __shared__ char sm[];
    const uint32_t sbase = smem_u32(sm);
    const int tid = threadIdx.x;
    const int wid = tid >> 5;
    const int lane = tid & 31;
    const int wr = wid >> 2;
    const int wc = wid & 3;
    const int m0 = blockIdx.y * 128;
    const int n0 = blockIdx.x * 128;

    float acc[4][4][4];
#pragma unroll
    for (int i = 0; i < 4; i++)
#pragma unroll
        for (int j = 0; j < 4; j++)
#pragma unroll
            for (int f = 0; f < 4; f++) acc[i][j][f] = 0.f;

    auto load_stage = [&](int kc, int stage) {
        const int kbase = kc * BK;
        const uint32_t sdst = sbase + stage * STAGE_B;
#pragma unroll
        for (int u = 0; u < 8; u++) {
            int idx = u * 256 + tid;
            int t = idx >> 10;
            int within = idx & 1023;
            int r = within >> 3;
            int ch = within & 7;
            const __half* base = (t == 0) ? A : B;
            int grow = ((t == 0) ? m0 : n0) + r;
            const void* src = base + (size_t)grow * KDIM + kbase + ch * 8;
            uint32_t dst = sdst + t * TILE_B + r * ROWB + ch * 16;
            asm volatile("cp.async.cg.shared.global [%0], [%1], 16;"
                         :: "r"(dst), "l"(src));
        }
        asm volatile("cp.async.commit_group;" ::: "memory");
    };

    load_stage(0, 0);
    load_stage(1, 1);

    const int sub = lane >> 3;
    const int rin = lane & 7;

    int stage = 0;
    int pstage = 2;
    for (int c = 0; c < NCH; c++) {
        asm volatile("cp.async.wait_group 1;" ::: "memory");
        __syncthreads();

        if (c + 2 < NCH)
            load_stage(c + 2, pstage);
        else
            asm volatile("cp.async.commit_group;" ::: "memory");

        const uint32_t sb = sbase + stage * STAGE_B;
        const uint32_t sA = sb;
        const uint32_t sB = sb + TILE_B;

#pragma unroll
        for (int ks = 0; ks < 4; ks++) {
            const int k0 = ks * 16;
            const int am = ((sub & 1) ? 8 : 0) + rin;
            const int ak = k0 + ((sub & 2) ? 8 : 0);
            uint32_t a[4][4];
#pragma unroll
            for (int mt = 0; mt < 4; mt++)
                ldsm_x4(a[mt], sA + (uint32_t)((wr * 64 + mt * 16 + am) * ROWB + ak * 2));
            const int bn = ((sub & 2) ? 8 : 0) + rin;
            const int bk = k0 + ((sub & 1) ? 8 : 0);
            uint32_t bb[2][4];
#pragma unroll
            for (int g = 0; g < 2; g++)
                ldsm_x4(bb[g], sB + (uint32_t)((wc * 32 + g * 16 + bn) * ROWB + bk * 2));
#pragma unroll
            for (int mt = 0; mt < 4; mt++)
#pragma unroll
                for (int nt = 0; nt < 4; nt++) {
                    const int g = nt >> 1, p = (nt & 1) * 2;
                    mma16816h(acc[mt][nt], a[mt], bb[g][p], bb[g][p + 1]);
                }
        }
        stage = (stage + 1 == NSTAGE) ? 0 : stage + 1;
        pstage = (pstage + 1 == NSTAGE) ? 0 : pstage + 1;
    }

    const int em = lane >> 2;
    const int en = (lane & 3) * 2;
#pragma unroll
    for (int mt = 0; mt < 4; mt++) {
#pragma unroll
        for (int nt = 0; nt < 4; nt++) {
            int n = n0 + wc * 32 + nt * 8 + en;
            float b0 = bias[n], b1 = bias[n + 1];
            int m = m0 + wr * 64 + mt * 16 + em;
            float o00 = acc[mt][nt][0] + b0, o01 = acc[mt][nt][1] + b1;
            float o10 = acc[mt][nt][2] + b0, o11 = acc[mt][nt][3] + b1;
            if (C16) {
                *(uint32_t*)(C16 + (size_t)m * N + n) = packh2(o00, o01);
                *(uint32_t*)(C16 + (size_t)(m + 8) * N + n) = packh2(o10, o11);
            } else {
                *(float2*)(C32 + (size_t)m * N + n) = make_float2(o00, o01);
                *(float2*)(C32 + (size_t)(m + 8) * N + n) = make_float2(o10, o11);
            }
        }
    }
}

// ---------------------------------------------------------------------------
// Tensor-core windowed attention, q-tile=128, 8 warps (16 queries each).
// K/V span 3 aligned 64-tiles (192 rows, r = key - (q0-64)).
// Each warp w visits ONLY chunks c = w..w+4 (its W=56 window) -> 5 chunks
// instead of 8: 37% fewer MMAs, half the CTAs, 25% less K/V traffic.
// ---------------------------------------------------------------------------
#define AROWB 144
#define VROWB 176
#define OFF_Q  0
#define OFF_K  18432                  // 128*144
#define OFF_V  46080                  // OFF_K + 192*144
#define SM_ATT (OFF_V + 192 * VROWB)  // 79872

__global__ __launch_bounds__(256) void attn_mma(
    const __half* __restrict__ qkv, __half* __restrict__ aout)
{
    extern __shared__ char sm[];
    const uint32_t sbase = smem_u32(sm);
    const int b = blockIdx.z;
    const int h = blockIdx.y;
    const int qt = blockIdx.x;
    const int q0 = qt * 128;
    const int tid = threadIdx.x;
    const int wid = tid >> 5;
    const int lane = tid & 31;

    const __half* qkvb = qkv + (size_t)(b * S_LEN) * (3 * D_MODEL) + h * HEAD_DIM;
    const int kskip = (qt == 0) ? 64 : 0;     // rows r<64 are key<0 when qt==0

    // ---- cp.async preamble ----
#pragma unroll
    for (int u = 0; u < 4; u++) {                      // Q: 128 rows
        int idx = u * 256 + tid;
        int r = idx >> 3, ch = idx & 7;
        const void* src = qkvb + (size_t)(q0 + r) * (3 * D_MODEL) + ch * 8;
        uint32_t dst = sbase + OFF_Q + r * AROWB + ch * 16;
        asm volatile("cp.async.cg.shared.global [%0], [%1], 16;" :: "r"(dst), "l"(src));
    }
#pragma unroll
    for (int u = 0; u < 6; u++) {                      // K: 192 rows
        int idx = u * 256 + tid;
        int r = idx >> 3, ch = idx & 7;
        if (r >= kskip) {
            const void* src = qkvb + (size_t)(q0 - 64 + r) * (3 * D_MODEL)
                              + D_MODEL + ch * 8;
            uint32_t dst = sbase + OFF_K + r * AROWB + ch * 16;
            asm volatile("cp.async.cg.shared.global [%0], [%1], 16;" :: "r"(dst), "l"(src));
        }
    }
#pragma unroll
    for (int u = 0; u < 6; u++) {                      // V: 192 rows
        int idx = u * 256 + tid;
        int r = idx >> 3, ch = idx & 7;
        if (r >= kskip) {
            const void* src = qkvb + (size_t)(q0 - 64 + r) * (3 * D_MODEL)
                              + 2 * D_MODEL + ch * 8;
            uint32_t dst = sbase + OFF_V + r * VROWB + ch * 16;
            asm volatile("cp.async.cg.shared.global [%0], [%1], 16;" :: "r"(dst), "l"(src));
        }
    }
    // V cols 64..79: col 64 = 1.0 (lval column), rest 0
    {
        uint32_t onezero = packh2(1.0f, 0.0f);
#pragma unroll
        for (int u = 0; u < 6; u++) {
            int w = u * 256 + tid;
            int r = w >> 3, cw = w & 7;
            *(uint32_t*)(sm + OFF_V + r * VROWB + 128 + cw * 4) = cw ? 0u : onezero;
        }
    }
    asm volatile("cp.async.commit_group;" ::: "memory");
    asm volatile("cp.async.wait_group 0;" ::: "memory");
    __syncthreads();

    const int sub = lane >> 3;
    const int rin = lane & 7;

    // Q a-fragments (this warp's 16 rows), resident
    uint32_t qa[4][4];
    {
        const int am = wid * 16 + ((sub & 1) ? 8 : 0) + rin;
#pragma unroll
        for (int ks = 0; ks < 4; ks++) {
            int ak = ks * 16 + ((sub & 2) ? 8 : 0);
            ldsm_x4(qa[ks], sbase + OFF_Q + am * AROWB + ak * 2);
        }
    }

    float out[9][4];
#pragma unroll
    for (int n = 0; n < 9; n++)
#pragma unroll
        for (int f = 0; f < 4; f++) out[n][f] = 0.f;

    const int qr = q0 + wid * 16 + (lane >> 2);

    // warp w needs key chunks c = w .. w+4 (keys r in [16w+8, 16w+79])
    const int cmin = (qt == 0) ? 4 : 0;
    int cstart = (wid < cmin) ? cmin : wid;
    const int cend = wid + 4;

    for (int c = cstart; c <= cend; c++) {
        const int krowbase = c * 16;

        // K b-fragments for this 16-key chunk
        uint32_t kb[4][4];
        {
            const int bn = krowbase + ((sub & 2) ? 8 : 0) + rin;
            const int bkoff = ((sub & 1) ? 8 : 0);
#pragma unroll
            for (int ks = 0; ks < 4; ks++)
                ldsm_x4(kb[ks], sbase + OFF_K
                        + (uint32_t)(bn * AROWB + (ks * 16 + bkoff) * 2));
        }

        // S = Q K^T
        float s[2][4];
#pragma unroll
        for (int ntl = 0; ntl < 2; ntl++)
#pragma unroll
            for (int f = 0; f < 4; f++) s[ntl][f] = 0.f;
#pragma unroll
        for (int ks = 0; ks < 4; ks++)
#pragma unroll
            for (int ntl = 0; ntl < 2; ntl++)
                mma16816h(s[ntl], qa[ks], kb[ks][ntl * 2], kb[ks][ntl * 2 + 1]);

        // bias + exp + pack P
        uint32_t pa[4];
#pragma unroll
        for (int ntl = 0; ntl < 2; ntl++) {
            const int key = q0 - 64 + krowbase + ntl * 8 + (lane & 3) * 2;
            float p0 = exp_bias(s[ntl][0], qr - key);
            float p1 = exp_bias(s[ntl][1], qr - key - 1);
            float p2 = exp_bias(s[ntl][2], qr + 8 - key);
            float p3 = exp_bias(s[ntl][3], qr + 8 - key - 1);
            pa[ntl * 2 + 0] = packh2(p0, p1);
            pa[ntl * 2 + 1] = packh2(p2, p3);
        }

        // PV via ldmatrix.trans; g=4 tile covers the lval (ones) column
        {
            const int vrow = krowbase + ((sub & 1) ? 8 : 0) + rin;
#pragma unroll
            for (int g = 0; g < 5; g++) {
                uint32_t vb[4];
                int vcol = g * 16 + ((sub & 2) ? 8 : 0);
                ldsm_x4_t(vb, sbase + OFF_V + (uint32_t)(vrow * VROWB + vcol * 2));
                if (g < 4) {
                    mma16816h(out[g * 2 + 0], pa, vb[0], vb[1]);
                    mma16816h(out[g * 2 + 1], pa, vb[2], vb[3]);
                } else {
                    mma16816h(out[8], pa, vb[0], vb[1]);
                }
            }
        }
    }

    // ---- epilogue: normalize by lval (output column 64), write fp16 ----
    float lv01 = __shfl_sync(0xffffffffu, out[8][0], lane & ~3);
    float lv23 = __shfl_sync(0xffffffffu, out[8][2], lane & ~3);
    const float inv01 = 1.f / lv01;
    const float inv23 = 1.f / lv23;

    const size_t r0base = ((size_t)(b * S_LEN) + qr) * KDIM + h * HEAD_DIM;
    const size_t r1base = r0base + (size_t)8 * KDIM;
#pragma unroll
    for (int n = 0; n < 8; n++) {
        const int dcol = n * 8 + (lane & 3) * 2;
        *(uint32_t*)(aout + r0base + dcol) = packh2(out[n][0] * inv01, out[n][1] * inv01);
        *(uint32_t*)(aout + r1base + dcol) = packh2(out[n][2] * inv23, out[n][3] * inv23);
    }
}

// ---------------------------------------------------------------------------
// Launch
// ---------------------------------------------------------------------------
extern "C" void kernel_launch(void* const* d_in, const int* in_sizes, int n_in,
                              void* d_out, int out_size)
{
    const float* x     = (const float*)d_in[0];
    const float* w_qkv = (const float*)d_in[1];
    const float* b_qkv = (const float*)d_in[2];
    const float* w_out = (const float*)d_in[3];
    const float* b_out = (const float*)d_in[4];
    float* out = (float*)d_out;

    __half *qkv16, *x16, *a16, *wq16, *wo16;
    cudaGetSymbolAddress((void**)&qkv16, g_qkv16);
    cudaGetSymbolAddress((void**)&x16, g_x16);
    cudaGetSymbolAddress((void**)&a16, g_a16);
    cudaGetSymbolAddress((void**)&wq16, g_wq16);
    cudaGetSymbolAddress((void**)&wo16, g_wo16);

    cudaFuncSetAttribute(tc_gemm_f16, cudaFuncAttributeMaxDynamicSharedMemorySize, SM_TOTAL);
    cudaFuncSetAttribute(attn_mma, cudaFuncAttributeMaxDynamicSharedMemorySize, SM_ATT);

    // 0) fp32 -> fp16
    convert_f16_all<<<(CVT_PER + 255) / 256, 256>>>(x, w_qkv, w_out, x16, wq16, wo16);

    // 1) QKV projection -> fp16 qkv buffer
    {
        dim3 grid(3 * D_MODEL / 128, M_ROWS / 128);   // (24, 64)
        tc_gemm_f16<<<grid, 256, SM_TOTAL>>>(x16, wq16, b_qkv, nullptr, qkv16,
                                             3 * D_MODEL);
    }

    // 2) Tensor-core windowed attention (q-tile 128, per-warp chunk ranges)
    {
        dim3 grid(S_LEN / 128, N_HEADS, BATCH);       // (16, 16, 4)
        attn_mma<<<grid, 256, SM_ATT>>>(qkv16, a16);
    }

    // 3) Output projection -> fp32 d_out
    {
        dim3 grid(D_MODEL / 128, M_ROWS / 128);       // (8, 64)
        tc_gemm_f16<<<grid, 256, SM_TOTAL>>>(a16, wo16, b_out, out, nullptr, D_MODEL);
    }
}